// round 17
// baseline (speedup 1.0000x reference)
#include <cuda_runtime.h>
#include <cstdint>

// GaussianVoxelizer: 2M gaussians -> 640K voxels argmax-by-opacity (min-index
// tiebreak), then per-voxel gather + analytic covariance inverse.
//
// output kernel (round 17): TWO-TILE SOFTWARE PIPELINE per warp. Each warp
// owns 64 voxels; BOTH lane-parallel gather batches (a[32], b[32]) are
// issued back-to-back before any consumption (~64 outstanding LDGs/warp,
// saturating the per-warp MLP cap), then tile0 completes (smem copy ->
// covinv -> writeback), the warp's smem rows are REUSED, and tile1
// completes. Tile1's gather latency hides behind tile0's compute+writeback.
// Warp-autonomous (no block barriers, round 16). Output has been at the
// ~5.95 TB/s traffic ceiling for 3 rounds; this targets the per-warp
// epilogue bubbles, the only non-traffic slack left.
//
// CODEGEN-CRITICAL: gather destinations live in local arrays consumed only
// after the loops (rounds 4-13: otherwise ptxas chunks the batch, MLP
// collapses). g_keys reset stays at the VERY END (rounds 4-10 bisect:
// earlier reset stores fence the gather scheduling).
//
// Voxel binning matches XLA's lowering of (x - vol_min) / 0.4: divide by
// constant folds to multiply by reciprocal; 1/0.4f == 2.5f exactly.

namespace {
constexpr int kH = 200, kW = 200, kD = 16;
constexpr int kV = kH * kW * kD;   // 640000
constexpr int kRow = 31;
constexpr int kBlk = 256;
constexpr int kVoxPerBlk = kBlk * 2;   // two tiles per warp
}

__device__ unsigned long long g_keys[kV];   // zero-initialized at module load

__device__ __forceinline__ int gv_flat(float x, float y, float z) {
    int vx = __float2int_rn(__fmul_rn(__fadd_rn(x, 40.0f), 2.5f));
    int vy = __float2int_rn(__fmul_rn(__fadd_rn(y, 40.0f), 2.5f));
    int vz = __float2int_rn(__fmul_rn(__fadd_rn(z, 1.0f), 2.5f));
    vx = min(max(vx, 0), kH - 1);
    vy = min(max(vy, 0), kW - 1);
    vz = min(max(vz, 0), kD - 1);
    return vx * (kW * kD) + vy * kD + vz;
}

__device__ __forceinline__ unsigned long long gv_key(float o, unsigned i) {
    return ((unsigned long long)__float_as_uint(o) << 32) |
           (unsigned long long)(0xFFFFFFFFu - i);
}

__global__ void gv_scatter_kernel(const float* __restrict__ means,
                                  const float* __restrict__ opac,
                                  int n) {
    int t = blockIdx.x * blockDim.x + threadIdx.x;
    int n4 = n >> 2;
    if (t < n4) {
        const float4* pm = reinterpret_cast<const float4*>(means) + 3 * t;
        float4 a = pm[0];
        float4 b = pm[1];
        float4 c = pm[2];
        float4 o = reinterpret_cast<const float4*>(opac)[t];
        unsigned i0 = 4 * t;

        int f0 = gv_flat(a.x, a.y, a.z);
        int f1 = gv_flat(a.w, b.x, b.y);
        int f2 = gv_flat(b.z, b.w, c.x);
        int f3 = gv_flat(c.y, c.z, c.w);

        atomicMax(&g_keys[f0], gv_key(o.x, i0 + 0));
        atomicMax(&g_keys[f1], gv_key(o.y, i0 + 1));
        atomicMax(&g_keys[f2], gv_key(o.z, i0 + 2));
        atomicMax(&g_keys[f3], gv_key(o.w, i0 + 3));
    } else if (t == n4 && (n & 3)) {
        for (int i = n4 * 4; i < n; i++) {
            int f = gv_flat(means[3 * i + 0], means[3 * i + 1],
                            means[3 * i + 2]);
            atomicMax(&g_keys[f], gv_key(opac[i], (unsigned)i));
        }
    }
}

// phase-2 worker: covinv + row finalization for one voxel's staged row.
__device__ __forceinline__ void gv_finish_row(float* row, int g, int idx,
                                              float opa,
                                              const float* empty_scalar) {
    float sx, sy, sz, qw, qx, qy, qz;

    if (g == kV) {
        row[0] = 0.0f; row[1] = 0.0f; row[2] = 2.2f;
        row[3] = 1.0f;
#pragma unroll
        for (int c = 4; c < 21; c++) row[c] = 0.0f;
        row[21] = empty_scalar[0];
        sx = 100.0f; sy = 100.0f; sz = 8.0f;
        qw = 1.0f; qx = 0.0f; qy = 0.0f; qz = 0.0f;
    } else if (idx >= 0) {
        row[3]  = opa;
        row[21] = 0.0f;
        sx = row[22]; sy = row[23]; sz = row[24];
        qw = row[25]; qx = row[26]; qy = row[27]; qz = row[28];
    } else {
#pragma unroll
        for (int c = 0; c < 22; c++) row[c] = 0.0f;
        sx = 1.0f; sy = 1.0f; sz = 1.0f;
        qw = 1.0f; qx = 0.0f; qy = 0.0f; qz = 0.0f;
    }

    float nrm = sqrtf(qw * qw + qx * qx + qy * qy + qz * qz);
    float inv = 1.0f / nrm;
    qw *= inv; qx *= inv; qy *= inv; qz *= inv;

    float r00 = 1.0f - 2.0f * (qy * qy + qz * qz);
    float r01 = 2.0f * (qx * qy - qw * qz);
    float r02 = 2.0f * (qx * qz + qw * qy);
    float r10 = 2.0f * (qx * qy + qw * qz);
    float r11 = 1.0f - 2.0f * (qx * qx + qz * qz);
    float r12 = 2.0f * (qy * qz - qw * qx);
    float r20 = 2.0f * (qx * qz - qw * qy);
    float r21 = 2.0f * (qy * qz + qw * qx);
    float r22 = 1.0f - 2.0f * (qx * qx + qy * qy);

    float a0 = 1.0f / (sx * sx);
    float a1 = 1.0f / (sy * sy);
    float a2 = 1.0f / (sz * sz);

    float c00 = r00 * r00 * a0 + r10 * r10 * a1 + r20 * r20 * a2;
    float c01 = r00 * r01 * a0 + r10 * r11 * a1 + r20 * r21 * a2;
    float c02 = r00 * r02 * a0 + r10 * r12 * a1 + r20 * r22 * a2;
    float c11 = r01 * r01 * a0 + r11 * r11 * a1 + r21 * r21 * a2;
    float c12 = r01 * r02 * a0 + r11 * r12 * a1 + r21 * r22 * a2;
    float c22 = r02 * r02 * a0 + r12 * r12 * a1 + r22 * r22 * a2;

    row[22] = c00; row[23] = c01; row[24] = c02;
    row[25] = c01; row[26] = c11; row[27] = c12;
    row[28] = c02; row[29] = c12; row[30] = c22;
}

__global__ void __launch_bounds__(kBlk)
gv_output_kernel(const float* __restrict__ means,
                 const float* __restrict__ opac,
                 const float* __restrict__ feats,
                 const float* __restrict__ scales,
                 const float* __restrict__ rots,
                 const float* __restrict__ empty_scalar,
                 float* __restrict__ out) {
    __shared__ float srows[kBlk * kRow];

    int tid  = threadIdx.x;
    int lane = tid & 31;
    int warp = tid >> 5;
    int wbeg0 = blockIdx.x * kVoxPerBlk + warp * 64;
    int wbeg1 = wbeg0 + 32;
    int g0 = wbeg0 + lane;
    int g1 = wbeg1 + lane;

    // keys -> (idx, opacity), both tiles
    unsigned long long k0 = (g0 < kV) ? g_keys[g0] : 0ull;
    unsigned long long k1 = (g1 < kV) ? g_keys[g1] : 0ull;
    int idx0 = (k0 != 0ull)
        ? (int)(0xFFFFFFFFu - (unsigned)(k0 & 0xFFFFFFFFull)) : -1;
    int idx1 = (k1 != 0ull)
        ? (int)(0xFFFFFFFFu - (unsigned)(k1 & 0xFFFFFFFFull)) : -1;
    float opa0 = __uint_as_float((unsigned)(k0 >> 32));
    float opa1 = __uint_as_float((unsigned)(k1 >> 32));

    // lane -> (source array, stride, offset, staging column)
    const float* bptr;
    int mul, off, col;
    if (lane < 3)       { bptr = means;  mul = 3;  off = lane;      col = lane; }
    else if (lane < 20) { bptr = feats;  mul = 17; off = lane - 3;  col = lane + 1; }
    else if (lane < 23) { bptr = scales; mul = 3;  off = lane - 20; col = lane + 2; }
    else if (lane < 27) { bptr = rots;   mul = 4;  off = lane - 23; col = lane + 2; }
    else                { bptr = means;  mul = 0;  off = 0;         col = 0; }
    bool active = (lane < 27);

    // BOTH gather batches issued up front: destinations a[32], b[32] stay
    // live until their respective copy loops -> ~64 LDGs in flight.
    float a[32], b[32];
#pragma unroll
    for (int v = 0; v < 32; v++) {
        int idx = __shfl_sync(0xFFFFFFFFu, idx0, v);
        a[v] = (active && idx >= 0) ? __ldg(bptr + mul * idx + off) : 0.0f;
    }
#pragma unroll
    for (int v = 0; v < 32; v++) {
        int idx = __shfl_sync(0xFFFFFFFFu, idx1, v);
        b[v] = (active && idx >= 0) ? __ldg(bptr + mul * idx + off) : 0.0f;
    }

    float* wrows = srows + (warp << 5) * kRow;   // this warp's 32 rows
    float* myrow = srows + tid * kRow;           // stride 31: conflict-free

    // ---- tile 0 ----
#pragma unroll
    for (int v = 0; v < 32; v++) {
        if (active) wrows[v * kRow + col] = a[v];
    }
    __syncwarp();
    if (g0 <= kV) gv_finish_row(myrow, g0, idx0, opa0, empty_scalar);
    __syncwarp();
    {
        int wrows_n = min(32, kV + 1 - wbeg0);
        if (wrows_n == 32) {
            const float4* ps = reinterpret_cast<const float4*>(wrows);
            float4* po = reinterpret_cast<float4*>(out + (size_t)wbeg0 * kRow);
#pragma unroll
            for (int e = lane; e < 32 * kRow / 4; e += 32) po[e] = ps[e];
        } else if (wrows_n > 0) {
            int nelem = wrows_n * kRow;
            float* po = out + (size_t)wbeg0 * kRow;
            for (int e = lane; e < nelem; e += 32) po[e] = wrows[e];
        }
    }
    __syncwarp();   // all lanes done reading tile0 rows before reuse

    // ---- tile 1 (reuses the same smem rows) ----
#pragma unroll
    for (int v = 0; v < 32; v++) {
        if (active) wrows[v * kRow + col] = b[v];
    }
    __syncwarp();
    if (g1 <= kV) gv_finish_row(myrow, g1, idx1, opa1, empty_scalar);
    __syncwarp();
    {
        int wrows_n = min(32, kV + 1 - wbeg1);
        if (wrows_n == 32) {
            const float4* ps = reinterpret_cast<const float4*>(wrows);
            float4* po = reinterpret_cast<float4*>(out + (size_t)wbeg1 * kRow);
#pragma unroll
            for (int e = lane; e < 32 * kRow / 4; e += 32) po[e] = ps[e];
        } else if (wrows_n > 0) {
            int nelem = wrows_n * kRow;
            float* po = out + (size_t)wbeg1 * kRow;
            for (int e = lane; e < nelem; e += 32) po[e] = wrows[e];
        }
    }

    // reset AFTER the hot path: zero-invariant for next graph replay.
    if (g0 < kV) g_keys[g0] = 0ull;
    if (g1 < kV) g_keys[g1] = 0ull;
}

extern "C" void kernel_launch(void* const* d_in, const int* in_sizes, int n_in,
                              void* d_out, int out_size) {
    const float* means        = (const float*)d_in[0];  // [N,3]
    const float* opac         = (const float*)d_in[1];  // [N,1]
    const float* feats        = (const float*)d_in[2];  // [N,17]
    const float* scales       = (const float*)d_in[3];  // [N,3]
    const float* rots         = (const float*)d_in[4];  // [N,4]
    const float* empty_scalar = (const float*)d_in[5];  // [1]
    float* out = (float*)d_out;                         // [1, V+1, 31]

    int n = in_sizes[0] / 3;

    int nthreads = n / 4 + 1;   // +1 thread handles any scalar tail
    gv_scatter_kernel<<<(nthreads + 255) / 256, 256>>>(means, opac, n);
    gv_output_kernel<<<(kV + 1 + kVoxPerBlk - 1) / kVoxPerBlk, kBlk>>>(
        means, opac, feats, scales, rots, empty_scalar, out);
}